// round 1
// baseline (speedup 1.0000x reference)
#include <cuda_runtime.h>
#include <cuda_bf16.h>

#define NU 8
#define MA 1024
#define NPTS (NU * MA)
#define NPAIRS 28      // NU*(NU-1)/2
#define IC 2           // i-chunks per unit (512 i each)
#define JC 32          // j-chunks per unit (32 j each)
#define JT 32          // j tile size
#define THREADS 256

__device__ float4 g_pts[NPTS];   // (X, Y, Z, c) pre-scaled for single-EX2 exponent

__device__ __forceinline__ unsigned long long pk2(float a, float b) {
    unsigned long long r;
    asm("mov.b64 %0, {%1, %2};" : "=l"(r) : "f"(a), "f"(b));
    return r;
}
__device__ __forceinline__ void upk2(float& a, float& b, unsigned long long v) {
    asm("mov.b64 {%0, %1}, %2;" : "=f"(a), "=f"(b) : "l"(v));
}
__device__ __forceinline__ unsigned long long fma2(unsigned long long a, unsigned long long b, unsigned long long c) {
    unsigned long long d;
    asm("fma.rn.f32x2 %0, %1, %2, %3;" : "=l"(d) : "l"(a), "l"(b), "l"(c));
    return d;
}
__device__ __forceinline__ unsigned long long add2(unsigned long long a, unsigned long long b) {
    unsigned long long d;
    asm("add.rn.f32x2 %0, %1, %2;" : "=l"(d) : "l"(a), "l"(b));
    return d;
}
__device__ __forceinline__ float ex2f(float x) {
    float r;
    asm("ex2.approx.f32 %0, %1;" : "=r"(*(unsigned*)&r) : "r"(*(unsigned*)&x));
    return r;
}

// ---------------------------------------------------------------------------
// Kernel 0: rotation matrices, transformed points (pre-scaled), L1 + L_com
// ---------------------------------------------------------------------------
__global__ void prep_kernel(const float* __restrict__ pos,
                            const float* __restrict__ euler,
                            const float* __restrict__ coords,
                            float* __restrict__ out) {
    __shared__ float Rsh[NU][9];
    __shared__ float Psh[NU][3];
    __shared__ float red[THREADS];
    const float LOG2E = 1.4426950408889634f;
    int tid = threadIdx.x;

    if (tid < NU) {
        float phi = euler[tid * 3 + 0];
        float the = euler[tid * 3 + 1];
        float psi = euler[tid * 3 + 2];
        float cp = cosf(phi), sp = sinf(phi);
        float ct = cosf(the), st = sinf(the);
        float cs = cosf(psi), ss = sinf(psi);
        // R = Rz(psi) @ Ry(theta) @ Rx(phi)
        Rsh[tid][0] = cs * ct;
        Rsh[tid][1] = -ss * cp + cs * st * sp;
        Rsh[tid][2] = ss * sp + cs * st * cp;
        Rsh[tid][3] = ss * ct;
        Rsh[tid][4] = cs * cp + ss * st * sp;
        Rsh[tid][5] = -cs * sp + ss * st * cp;
        Rsh[tid][6] = -st;
        Rsh[tid][7] = ct * sp;
        Rsh[tid][8] = ct * cp;
        Psh[tid][0] = pos[tid * 3 + 0];
        Psh[tid][1] = pos[tid * 3 + 1];
        Psh[tid][2] = pos[tid * 3 + 2];
    }
    __syncthreads();

    const float S = sqrtf(2.0f * LOG2E);
    float l1 = 0.0f;
    for (int idx = tid; idx < NPTS; idx += THREADS) {
        int u = idx >> 10;
        int m = idx & (MA - 1);
        float cx = coords[m * 3 + 0];
        float cy = coords[m * 3 + 1];
        float cz = coords[m * 3 + 2];
        const float* R = Rsh[u];
        float px = fmaf(R[0], cx, fmaf(R[1], cy, fmaf(R[2], cz, Psh[u][0])));
        float py = fmaf(R[3], cx, fmaf(R[4], cy, fmaf(R[5], cz, Psh[u][1])));
        float pz = fmaf(R[6], cx, fmaf(R[7], cy, fmaf(R[8], cz, Psh[u][2])));
        float sq = px * px + py * py + pz * pz;
        l1 += sq;
        float4 o;
        o.x = S * px;
        o.y = S * py;
        o.z = S * pz;
        o.w = 0.5f * LOG2E - LOG2E * sq;   // so c_i + c_j + dot = log2e*(1 - d2)
        g_pts[idx] = o;
    }

    red[tid] = l1;
    __syncthreads();
    for (int s = THREADS / 2; s > 0; s >>= 1) {
        if (tid < s) red[tid] += red[tid + s];
        __syncthreads();
    }
    if (tid == 0) {
        float cx = 0.f, cy = 0.f, cz = 0.f;
        for (int u = 0; u < NU; u++) { cx += Psh[u][0]; cy += Psh[u][1]; cz += Psh[u][2]; }
        float lcom = cx * cx + cy * cy + cz * cz;          // ALPHA = 1
        out[0] = red[0] / (float)NU + lcom;                // L1 + L_com
    }
}

// ---------------------------------------------------------------------------
// Kernel 1: masked pairwise Gaussian-penalty sum (MUFU.EX2 bound)
// Each block: one (u,v) unit pair, 512-i chunk x 32-j tile.
// ---------------------------------------------------------------------------
__global__ void __launch_bounds__(THREADS) pair_kernel(float* __restrict__ out) {
    __shared__ __align__(16) float sj[4][JT];   // SoA: X, Y, Z, c
    __shared__ float wsum[THREADS / 32];

    int b = blockIdx.x;
    int p  = b / (IC * JC);
    int r  = b % (IC * JC);
    int ic = r / JC;
    int jc = r % JC;

    // pair index -> (u, v), u < v
    int rem = p, u = 0, row = NU - 1;
    while (rem >= row) { rem -= row; row--; u++; }
    int v = u + 1 + rem;

    int tid = threadIdx.x;

    // Stage j tile into SoA shared (LDS.64-friendly for f32x2 packing)
    if (tid < JT) {
        float4 q = g_pts[v * MA + jc * JT + tid];
        sj[0][tid] = q.x;
        sj[1][tid] = q.y;
        sj[2][tid] = q.z;
        sj[3][tid] = q.w;
    }
    __syncthreads();

    // Two i points per thread (coalesced LDG.128)
    int ibase = u * MA + ic * (MA / IC) + tid;
    float4 a0 = g_pts[ibase];
    float4 a1 = g_pts[ibase + THREADS];

    unsigned long long DX0 = pk2(a0.x, a0.x), DY0 = pk2(a0.y, a0.y),
                       DZ0 = pk2(a0.z, a0.z), DC0 = pk2(a0.w, a0.w);
    unsigned long long DX1 = pk2(a1.x, a1.x), DY1 = pk2(a1.y, a1.y),
                       DZ1 = pk2(a1.z, a1.z), DC1 = pk2(a1.w, a1.w);

    const unsigned long long* xp = reinterpret_cast<const unsigned long long*>(sj[0]);
    const unsigned long long* yp = reinterpret_cast<const unsigned long long*>(sj[1]);
    const unsigned long long* zp = reinterpret_cast<const unsigned long long*>(sj[2]);
    const unsigned long long* cp = reinterpret_cast<const unsigned long long*>(sj[3]);

    float s0 = 0.f, s1 = 0.f, s2 = 0.f, s3 = 0.f;

#pragma unroll
    for (int t = 0; t < JT / 2; t++) {
        unsigned long long XJ = xp[t];
        unsigned long long YJ = yp[t];
        unsigned long long ZJ = zp[t];
        unsigned long long CJ = cp[t];

        unsigned long long t0 = add2(DC0, CJ);
        t0 = fma2(DX0, XJ, t0);
        t0 = fma2(DY0, YJ, t0);
        t0 = fma2(DZ0, ZJ, t0);
        float lo0, hi0;
        upk2(lo0, hi0, t0);
        s0 += ex2f(lo0);
        s1 += ex2f(hi0);

        unsigned long long t1 = add2(DC1, CJ);
        t1 = fma2(DX1, XJ, t1);
        t1 = fma2(DY1, YJ, t1);
        t1 = fma2(DZ1, ZJ, t1);
        float lo1, hi1;
        upk2(lo1, hi1, t1);
        s2 += ex2f(lo1);
        s3 += ex2f(hi1);
    }

    // Block reduce -> one atomic per block
    float s = (s0 + s1) + (s2 + s3);
#pragma unroll
    for (int o = 16; o > 0; o >>= 1)
        s += __shfl_xor_sync(0xFFFFFFFFu, s, o);
    if ((tid & 31) == 0) wsum[tid >> 5] = s;
    __syncthreads();
    if (tid == 0) {
        float bs = 0.f;
#pragma unroll
        for (int w = 0; w < THREADS / 32; w++) bs += wsum[w];
        atomicAdd(out, 0.5f * bs);   // LAMBDA1 = 0.5
    }
}

extern "C" void kernel_launch(void* const* d_in, const int* in_sizes, int n_in,
                              void* d_out, int out_size) {
    const float* positions = (const float*)d_in[0];
    const float* euler     = (const float*)d_in[1];
    const float* coords    = (const float*)d_in[2];
    float* out = (float*)d_out;

    prep_kernel<<<1, THREADS>>>(positions, euler, coords, out);
    pair_kernel<<<NPAIRS * IC * JC, THREADS>>>(out);
}

// round 2
// speedup vs baseline: 1.2408x; 1.2408x over previous
#include <cuda_runtime.h>
#include <cuda_bf16.h>

#define NU 8
#define MA 1024
#define NPTS (NU * MA)
#define NPAIRS 28      // NU*(NU-1)/2
#define JC 32          // j-chunks per unit
#define JT 32          // j tile size
#define IPT 4          // i points per thread
#define THREADS 256
#define PREP_BLOCKS 32

__device__ float4 g_pts[NPTS];     // (X, Y, Z, c) pre-scaled: X=S*px, c=log2e*(0.5-|p|^2)
__device__ float g_l1p[PREP_BLOCKS];
__device__ unsigned g_ticket;      // starts 0; last prep block resets to 0 each run

__device__ __forceinline__ unsigned long long pk2(float a, float b) {
    unsigned long long r;
    asm("mov.b64 %0, {%1, %2};" : "=l"(r) : "f"(a), "f"(b));
    return r;
}
__device__ __forceinline__ void upk2(float& a, float& b, unsigned long long v) {
    asm("mov.b64 {%0, %1}, %2;" : "=f"(a), "=f"(b) : "l"(v));
}
__device__ __forceinline__ unsigned long long fma2(unsigned long long a, unsigned long long b, unsigned long long c) {
    unsigned long long d;
    asm("fma.rn.f32x2 %0, %1, %2, %3;" : "=l"(d) : "l"(a), "l"(b), "l"(c));
    return d;
}
__device__ __forceinline__ float ex2f(float x) {
    float r;
    asm("ex2.approx.f32 %0, %1;" : "=r"(*(unsigned*)&r) : "r"(*(unsigned*)&x));
    return r;
}

// ---------------------------------------------------------------------------
// Kernel 0: parallel prep. 32 blocks x 256 threads, one point per thread.
// Writes g_pts, and via ticket-finalize writes out[0] = L1 + L_com.
// ---------------------------------------------------------------------------
__global__ void __launch_bounds__(THREADS) prep_kernel(const float* __restrict__ pos,
                            const float* __restrict__ euler,
                            const float* __restrict__ coords,
                            float* __restrict__ out) {
    __shared__ float Rsh[NU][9];
    __shared__ float Psh[NU][3];
    __shared__ float wred[THREADS / 32];
    __shared__ unsigned s_done;
    const float LOG2E = 1.4426950408889634f;
    int tid = threadIdx.x;
    int b = blockIdx.x;

    if (tid < NU) {
        float phi = euler[tid * 3 + 0];
        float the = euler[tid * 3 + 1];
        float psi = euler[tid * 3 + 2];
        float cp = cosf(phi), sp = sinf(phi);
        float ct = cosf(the), st = sinf(the);
        float cs = cosf(psi), ss = sinf(psi);
        // R = Rz(psi) @ Ry(theta) @ Rx(phi)
        Rsh[tid][0] = cs * ct;
        Rsh[tid][1] = -ss * cp + cs * st * sp;
        Rsh[tid][2] = ss * sp + cs * st * cp;
        Rsh[tid][3] = ss * ct;
        Rsh[tid][4] = cs * cp + ss * st * sp;
        Rsh[tid][5] = -cs * sp + ss * st * cp;
        Rsh[tid][6] = -st;
        Rsh[tid][7] = ct * sp;
        Rsh[tid][8] = ct * cp;
        Psh[tid][0] = pos[tid * 3 + 0];
        Psh[tid][1] = pos[tid * 3 + 1];
        Psh[tid][2] = pos[tid * 3 + 2];
    }
    __syncthreads();

    const float S = 1.6986436005760381f;   // sqrt(2*log2e)
    int idx = b * THREADS + tid;
    int u = idx >> 10;
    int m = idx & (MA - 1);
    float cx = coords[m * 3 + 0];
    float cy = coords[m * 3 + 1];
    float cz = coords[m * 3 + 2];
    const float* R = Rsh[u];
    float px = fmaf(R[0], cx, fmaf(R[1], cy, fmaf(R[2], cz, Psh[u][0])));
    float py = fmaf(R[3], cx, fmaf(R[4], cy, fmaf(R[5], cz, Psh[u][1])));
    float pz = fmaf(R[6], cx, fmaf(R[7], cy, fmaf(R[8], cz, Psh[u][2])));
    float sq = px * px + py * py + pz * pz;
    float4 o;
    o.x = S * px;
    o.y = S * py;
    o.z = S * pz;
    o.w = LOG2E * (0.5f - sq);
    g_pts[idx] = o;

    // block reduce of sq -> g_l1p[b]
    float l1 = sq;
#pragma unroll
    for (int off = 16; off > 0; off >>= 1)
        l1 += __shfl_xor_sync(0xFFFFFFFFu, l1, off);
    if ((tid & 31) == 0) wred[tid >> 5] = l1;
    __syncthreads();
    if (tid == 0) {
        float bs = 0.f;
#pragma unroll
        for (int w = 0; w < THREADS / 32; w++) bs += wred[w];
        g_l1p[b] = bs;
        __threadfence();
        s_done = atomicAdd(&g_ticket, 1u);
    }
    __syncthreads();

    // last block finalizes L1 + L_com into out[0]
    if (s_done == PREP_BLOCKS - 1 && tid < 32) {
        float v = (tid < PREP_BLOCKS) ? g_l1p[tid] : 0.0f;
#pragma unroll
        for (int off = 16; off > 0; off >>= 1)
            v += __shfl_xor_sync(0xFFFFFFFFu, v, off);
        if (tid == 0) {
            float ccx = 0.f, ccy = 0.f, ccz = 0.f;
#pragma unroll
            for (int uu = 0; uu < NU; uu++) { ccx += Psh[uu][0]; ccy += Psh[uu][1]; ccz += Psh[uu][2]; }
            float lcom = ccx * ccx + ccy * ccy + ccz * ccz;     // ALPHA = 1
            out[0] = v / (float)NU + lcom;                      // L1 + L_com
            g_ticket = 0;                                       // reset for next graph replay
        }
    }
}

// ---------------------------------------------------------------------------
// Kernel 1: masked pairwise Gaussian-penalty sum. Target: MUFU.EX2 bound.
// Each block: one (u,v) pair, full 1024-i (4 per thread) x 32-j tile.
// pen = exp2(c_i) * exp2(c_j + dot(Pi', Pj'))
// ---------------------------------------------------------------------------
__global__ void __launch_bounds__(THREADS) pair_kernel(float* __restrict__ out) {
    __shared__ __align__(16) float sj[4][JT];   // SoA: X, Y, Z, c
    __shared__ float wsum[THREADS / 32];

    int b = blockIdx.x;
    int p  = b >> 5;          // pair index
    int jc = b & 31;          // j chunk

    // pair index -> (u, v), u < v
    int rem = p, u = 0, row = NU - 1;
    while (rem >= row) { rem -= row; row--; u++; }
    int v = u + 1 + rem;

    int tid = threadIdx.x;

    if (tid < JT) {
        float4 q = g_pts[v * MA + jc * JT + tid];
        sj[0][tid] = q.x;
        sj[1][tid] = q.y;
        sj[2][tid] = q.z;
        sj[3][tid] = q.w;
    }
    __syncthreads();

    // 4 i points per thread (coalesced)
    int ibase = u * MA + tid;
    float4 a0 = g_pts[ibase];
    float4 a1 = g_pts[ibase + THREADS];
    float4 a2 = g_pts[ibase + 2 * THREADS];
    float4 a3 = g_pts[ibase + 3 * THREADS];

    unsigned long long DX0 = pk2(a0.x, a0.x), DY0 = pk2(a0.y, a0.y), DZ0 = pk2(a0.z, a0.z);
    unsigned long long DX1 = pk2(a1.x, a1.x), DY1 = pk2(a1.y, a1.y), DZ1 = pk2(a1.z, a1.z);
    unsigned long long DX2 = pk2(a2.x, a2.x), DY2 = pk2(a2.y, a2.y), DZ2 = pk2(a2.z, a2.z);
    unsigned long long DX3 = pk2(a3.x, a3.x), DY3 = pk2(a3.y, a3.y), DZ3 = pk2(a3.z, a3.z);
    float e0 = ex2f(a0.w), e1 = ex2f(a1.w), e2 = ex2f(a2.w), e3 = ex2f(a3.w);

    const unsigned long long* xp = reinterpret_cast<const unsigned long long*>(sj[0]);
    const unsigned long long* yp = reinterpret_cast<const unsigned long long*>(sj[1]);
    const unsigned long long* zp = reinterpret_cast<const unsigned long long*>(sj[2]);
    const unsigned long long* cp = reinterpret_cast<const unsigned long long*>(sj[3]);

    float s0a = 0.f, s0b = 0.f, s1a = 0.f, s1b = 0.f;
    float s2a = 0.f, s2b = 0.f, s3a = 0.f, s3b = 0.f;

#pragma unroll
    for (int t = 0; t < JT / 2; t++) {
        unsigned long long XJ = xp[t];
        unsigned long long YJ = yp[t];
        unsigned long long ZJ = zp[t];
        unsigned long long CJ = cp[t];
        float lo, hi;

        unsigned long long t0 = fma2(DX0, XJ, CJ);
        t0 = fma2(DY0, YJ, t0);
        t0 = fma2(DZ0, ZJ, t0);
        upk2(lo, hi, t0);
        s0a = fmaf(e0, ex2f(lo), s0a);
        s0b = fmaf(e0, ex2f(hi), s0b);

        unsigned long long t1 = fma2(DX1, XJ, CJ);
        t1 = fma2(DY1, YJ, t1);
        t1 = fma2(DZ1, ZJ, t1);
        upk2(lo, hi, t1);
        s1a = fmaf(e1, ex2f(lo), s1a);
        s1b = fmaf(e1, ex2f(hi), s1b);

        unsigned long long t2 = fma2(DX2, XJ, CJ);
        t2 = fma2(DY2, YJ, t2);
        t2 = fma2(DZ2, ZJ, t2);
        upk2(lo, hi, t2);
        s2a = fmaf(e2, ex2f(lo), s2a);
        s2b = fmaf(e2, ex2f(hi), s2b);

        unsigned long long t3 = fma2(DX3, XJ, CJ);
        t3 = fma2(DY3, YJ, t3);
        t3 = fma2(DZ3, ZJ, t3);
        upk2(lo, hi, t3);
        s3a = fmaf(e3, ex2f(lo), s3a);
        s3b = fmaf(e3, ex2f(hi), s3b);
    }

    float s = ((s0a + s0b) + (s1a + s1b)) + ((s2a + s2b) + (s3a + s3b));
#pragma unroll
    for (int o = 16; o > 0; o >>= 1)
        s += __shfl_xor_sync(0xFFFFFFFFu, s, o);
    if ((tid & 31) == 0) wsum[tid >> 5] = s;
    __syncthreads();
    if (tid == 0) {
        float bs = 0.f;
#pragma unroll
        for (int w = 0; w < THREADS / 32; w++) bs += wsum[w];
        atomicAdd(out, 0.5f * bs);   // LAMBDA1 = 0.5
    }
}

extern "C" void kernel_launch(void* const* d_in, const int* in_sizes, int n_in,
                              void* d_out, int out_size) {
    const float* positions = (const float*)d_in[0];
    const float* euler     = (const float*)d_in[1];
    const float* coords    = (const float*)d_in[2];
    float* out = (float*)d_out;

    prep_kernel<<<PREP_BLOCKS, THREADS>>>(positions, euler, coords, out);
    pair_kernel<<<NPAIRS * JC, THREADS>>>(out);
}

// round 3
// speedup vs baseline: 1.3772x; 1.1099x over previous
#include <cuda_runtime.h>
#include <cuda_bf16.h>

#define NU 8
#define MA 1024
#define NPAIRS 28              // NU*(NU-1)/2
#define IH 2                   // i halves per pair
#define JC 32                  // j chunks per unit
#define JT 32                  // j tile size
#define THREADS 256
#define PAIR_BLOCKS (NPAIRS * IH * JC)   // 1792
#define TOTAL_BLOCKS (PAIR_BLOCKS + NU)  // +8 L1 blocks

__device__ float g_acc;        // single accumulator; reset by finalizer
__device__ unsigned g_ticket;  // arrival counter; reset by finalizer

__device__ __forceinline__ unsigned long long pk2(float a, float b) {
    unsigned long long r;
    asm("mov.b64 %0, {%1, %2};" : "=l"(r) : "f"(a), "f"(b));
    return r;
}
__device__ __forceinline__ void upk2(float& a, float& b, unsigned long long v) {
    asm("mov.b64 {%0, %1}, %2;" : "=f"(a), "=f"(b) : "l"(v));
}
__device__ __forceinline__ unsigned long long fma2(unsigned long long a, unsigned long long b, unsigned long long c) {
    unsigned long long d;
    asm("fma.rn.f32x2 %0, %1, %2, %3;" : "=l"(d) : "l"(a), "l"(b), "l"(c));
    return d;
}
__device__ __forceinline__ float ex2f(float x) {
    float r;
    asm("ex2.approx.f32 %0, %1;" : "=r"(*(unsigned*)&r) : "r"(*(unsigned*)&x));
    return r;
}

// Build rotation matrices + positions into shared (threads 0..7, one unit each)
__device__ __forceinline__ void build_R(float (*Rsh)[12],
                                        const float* __restrict__ pos,
                                        const float* __restrict__ euler,
                                        int tid) {
    if (tid < NU) {
        float phi = euler[tid * 3 + 0];
        float the = euler[tid * 3 + 1];
        float psi = euler[tid * 3 + 2];
        float cp = __cosf(phi), sp = __sinf(phi);
        float ct = __cosf(the), st = __sinf(the);
        float cs = __cosf(psi), ss = __sinf(psi);
        // R = Rz(psi) @ Ry(theta) @ Rx(phi)
        Rsh[tid][0] = cs * ct;
        Rsh[tid][1] = -ss * cp + cs * st * sp;
        Rsh[tid][2] = ss * sp + cs * st * cp;
        Rsh[tid][3] = ss * ct;
        Rsh[tid][4] = cs * cp + ss * st * sp;
        Rsh[tid][5] = -cs * sp + ss * st * cp;
        Rsh[tid][6] = -st;
        Rsh[tid][7] = ct * sp;
        Rsh[tid][8] = ct * cp;
        Rsh[tid][9]  = pos[tid * 3 + 0];
        Rsh[tid][10] = pos[tid * 3 + 1];
        Rsh[tid][11] = pos[tid * 3 + 2];
    }
}

// Transform atom m with unit u's rotation+position
__device__ __forceinline__ void xform(const float (*Rsh)[12],
                                      const float* __restrict__ coords,
                                      int u, int m,
                                      float& px, float& py, float& pz, float& sq) {
    float cx = coords[m * 3 + 0];
    float cy = coords[m * 3 + 1];
    float cz = coords[m * 3 + 2];
    const float* R = Rsh[u];
    px = fmaf(R[0], cx, fmaf(R[1], cy, fmaf(R[2], cz, R[9])));
    py = fmaf(R[3], cx, fmaf(R[4], cy, fmaf(R[5], cz, R[10])));
    pz = fmaf(R[6], cx, fmaf(R[7], cy, fmaf(R[8], cz, R[11])));
    sq = px * px + py * py + pz * pz;
}

// ---------------------------------------------------------------------------
// Single fused kernel.
// Blocks [0, 1792): pair tiles. Block b: pair p = b>>6, i-half = (b>>5)&1,
//   j-chunk = b&31. Computes 512i x 32j masked Gaussian penalties.
// Blocks [1792, 1800): L1 per unit (+ L_com in the first one).
// All partial results -> atomicAdd(g_acc). Last-arriving block writes out[0].
// pen = exp2(c_i) * exp2(c_j + dot(Pi', Pj')),  P' = sqrt(2*log2e)*p,
// c = log2e*(0.5 - |p|^2)   =>  product = exp(-(d2 - 1))
// ---------------------------------------------------------------------------
__global__ void __launch_bounds__(THREADS) fused_kernel(const float* __restrict__ pos,
                                                        const float* __restrict__ euler,
                                                        const float* __restrict__ coords,
                                                        float* __restrict__ out) {
    __shared__ float Rsh[NU][12];
    __shared__ __align__(16) float sj[4][JT];   // SoA j tile: X, Y, Z, c
    __shared__ float wsum[THREADS / 32];

    const float LOG2E = 1.4426950408889634f;
    const float S = 1.6986436005760381f;        // sqrt(2*log2e)
    int tid = threadIdx.x;
    int b = blockIdx.x;

    build_R(Rsh, pos, euler, tid);
    __syncthreads();

    float blockContrib = 0.0f;   // value thread 0 will atomicAdd

    if (b < PAIR_BLOCKS) {
        int p  = b >> 6;
        int ih = (b >> 5) & 1;
        int jc = b & 31;
        // pair index -> (u, v), u < v
        int rem = p, u = 0, row = NU - 1;
        while (rem >= row) { rem -= row; row--; u++; }
        int v = u + 1 + rem;

        // Stage j tile (unit v)
        if (tid < JT) {
            float px, py, pz, sq;
            xform(Rsh, coords, v, jc * JT + tid, px, py, pz, sq);
            sj[0][tid] = S * px;
            sj[1][tid] = S * py;
            sj[2][tid] = S * pz;
            sj[3][tid] = LOG2E * (0.5f - sq);
        }

        // i points (unit u): 2 per thread
        float px0, py0, pz0, sq0, px1, py1, pz1, sq1;
        xform(Rsh, coords, u, ih * 512 + tid,        px0, py0, pz0, sq0);
        xform(Rsh, coords, u, ih * 512 + tid + 256,  px1, py1, pz1, sq1);

        unsigned long long DX0 = pk2(S * px0, S * px0), DY0 = pk2(S * py0, S * py0), DZ0 = pk2(S * pz0, S * pz0);
        unsigned long long DX1 = pk2(S * px1, S * px1), DY1 = pk2(S * py1, S * py1), DZ1 = pk2(S * pz1, S * pz1);
        float e0 = ex2f(LOG2E * (0.5f - sq0));
        float e1 = ex2f(LOG2E * (0.5f - sq1));

        __syncthreads();

        const unsigned long long* xp = reinterpret_cast<const unsigned long long*>(sj[0]);
        const unsigned long long* yp = reinterpret_cast<const unsigned long long*>(sj[1]);
        const unsigned long long* zp = reinterpret_cast<const unsigned long long*>(sj[2]);
        const unsigned long long* cp = reinterpret_cast<const unsigned long long*>(sj[3]);

        float s0a = 0.f, s0b = 0.f, s1a = 0.f, s1b = 0.f;

#pragma unroll
        for (int t = 0; t < JT / 2; t++) {
            unsigned long long XJ = xp[t];
            unsigned long long YJ = yp[t];
            unsigned long long ZJ = zp[t];
            unsigned long long CJ = cp[t];
            float lo, hi;

            unsigned long long t0 = fma2(DX0, XJ, CJ);
            t0 = fma2(DY0, YJ, t0);
            t0 = fma2(DZ0, ZJ, t0);
            upk2(lo, hi, t0);
            s0a = fmaf(e0, ex2f(lo), s0a);
            s0b = fmaf(e0, ex2f(hi), s0b);

            unsigned long long t1 = fma2(DX1, XJ, CJ);
            t1 = fma2(DY1, YJ, t1);
            t1 = fma2(DZ1, ZJ, t1);
            upk2(lo, hi, t1);
            s1a = fmaf(e1, ex2f(lo), s1a);
            s1b = fmaf(e1, ex2f(hi), s1b);
        }

        float s = (s0a + s0b) + (s1a + s1b);
#pragma unroll
        for (int o = 16; o > 0; o >>= 1)
            s += __shfl_xor_sync(0xFFFFFFFFu, s, o);
        if ((tid & 31) == 0) wsum[tid >> 5] = s;
        __syncthreads();
        if (tid == 0) {
            float bs = 0.f;
#pragma unroll
            for (int w = 0; w < THREADS / 32; w++) bs += wsum[w];
            blockContrib = 0.5f * bs;      // LAMBDA1 = 0.5
        }
    } else {
        // L1 block for unit u (+ L_com in the u==0 block)
        int u = b - PAIR_BLOCKS;
        float l1 = 0.0f;
#pragma unroll
        for (int k = 0; k < 4; k++) {
            float px, py, pz, sq;
            xform(Rsh, coords, u, k * 256 + tid, px, py, pz, sq);
            l1 += sq;
        }
#pragma unroll
        for (int o = 16; o > 0; o >>= 1)
            l1 += __shfl_xor_sync(0xFFFFFFFFu, l1, o);
        if ((tid & 31) == 0) wsum[tid >> 5] = l1;
        __syncthreads();
        if (tid == 0) {
            float bs = 0.f;
#pragma unroll
            for (int w = 0; w < THREADS / 32; w++) bs += wsum[w];
            blockContrib = bs / (float)NU;      // contribution to L1 mean
            if (u == 0) {
                float ccx = 0.f, ccy = 0.f, ccz = 0.f;
#pragma unroll
                for (int uu = 0; uu < NU; uu++) {
                    ccx += Rsh[uu][9]; ccy += Rsh[uu][10]; ccz += Rsh[uu][11];
                }
                blockContrib += ccx * ccx + ccy * ccy + ccz * ccz;   // ALPHA = 1
            }
        }
    }

    // Accumulate + ticket finalize (thread 0 of every block)
    if (tid == 0) {
        atomicAdd(&g_acc, blockContrib);
        __threadfence();
        unsigned old = atomicAdd(&g_ticket, 1u);
        if (old == TOTAL_BLOCKS - 1) {
            __threadfence();
            float total = *((volatile float*)&g_acc);
            out[0] = total;
            g_acc = 0.0f;        // reset for next graph replay
            g_ticket = 0u;
        }
    }
}

extern "C" void kernel_launch(void* const* d_in, const int* in_sizes, int n_in,
                              void* d_out, int out_size) {
    const float* positions = (const float*)d_in[0];
    const float* euler     = (const float*)d_in[1];
    const float* coords    = (const float*)d_in[2];
    float* out = (float*)d_out;

    fused_kernel<<<TOTAL_BLOCKS, THREADS>>>(positions, euler, coords, out);
}